// round 12
// baseline (speedup 1.0000x reference)
#include <cuda_runtime.h>
#include <cuda_bf16.h>
#include <cstdint>
#include <math.h>

#define B_TOTAL 16384
#define NTREE 64
#define NNODES 63
#define NCLS 10

__device__ unsigned char g_xf[128 * 8 * 16384]; // [tile128][kc8][hi 16K] A-frag order
__device__ unsigned char g_wf[64 * 8 * 8192];   // [tree][kc8][hi 8K] B-frag, n-tile-paired
__device__ int g_missing[B_TOTAL];
__device__ float g_attn[NTREE * B_TOTAL];

__device__ __forceinline__ uint32_t smem_u32(const void* p) {
    uint32_t a;
    asm("{ .reg .u64 t; cvta.to.shared.u64 t, %1; cvt.u32.u64 %0, t; }" : "=r"(a) : "l"(p));
    return a;
}
#define CP16(s, g) asm volatile("cp.async.cg.shared.global [%0], [%1], 16;" :: "r"(s), "l"(g))
#define CPCOMMIT() asm volatile("cp.async.commit_group;")
#define CPWAIT1() asm volatile("cp.async.wait_group 1;")
#define CPWAIT0() asm volatile("cp.async.wait_group 0;")
#define MMA2(c, a, b0, b1) asm volatile( \
    "mma.sync.aligned.m16n8k16.row.col.f32.bf16.bf16.f32 " \
    "{%0,%1,%2,%3},{%4,%5,%6,%7},{%8,%9},{%0,%1,%2,%3};" \
    : "+f"((c)[0]), "+f"((c)[1]), "+f"((c)[2]), "+f"((c)[3]) \
    : "r"((a).x), "r"((a).y), "r"((a).z), "r"((a).w), "r"(b0), "r"(b1))

// smem layout
#define OFF_X 0u          // 2 x 32768 (2 kc per stage)
#define OFF_W 65536u      // 2 x 32768 (2 trees x 16KB [2 kc])
#define OFF_LG 131072u    // logits 128 x 144 floats (73728) / pred staging
#define OFF_LEAF 204800u  // 2 x 5120
#define SMEM_SZ 215040u
#define LGP 144

// ---------- prep x: NaN-clean + bf16 hi in A-fragment order ----------
__global__ __launch_bounds__(256) void k_prep_x(const float* __restrict__ x) {
    __shared__ __align__(16) unsigned char stage[16384];
    const int tile = blockIdx.x >> 3, kc = blockIdx.x & 7, tid = threadIdx.x;
    for (int e = tid; e < 8192; e += 256) {
        int r = e >> 6, j = e & 63;
        int row = tile * 128 + r;
        float v = x[row * 512 + kc * 64 + j];
        if (v != v) { v = 0.f; atomicOr(&g_missing[row], 1); }
        __nv_bfloat16 h = __float2bfloat16(v);
        int mtile = r >> 4, row16 = r & 15, g = row16 & 7, half = row16 >> 3;
        int kstep = j >> 4, kk = j & 15, tg = (kk >> 1) & 3, khalf = kk >> 3, klo = kk & 1;
        int t = g * 4 + tg, reg = half + 2 * khalf;
        uint32_t off = (uint32_t)(((kstep * 8 + mtile) * 32 + t) * 16 + reg * 4 + klo * 2);
        *(__nv_bfloat16*)(stage + off) = h;
    }
    __syncthreads();
    uint4* dst = (uint4*)(g_xf + (size_t)blockIdx.x * 16384);
    const uint4* src = (const uint4*)stage;
    for (int e = tid; e < 1024; e += 256) dst[e] = src[e];
}

// ---------- prep w: bf16 hi, B-fragment order with paired n-tiles (16B/lane) ----------
__global__ __launch_bounds__(256) void k_prep_w(const float* __restrict__ tw) {
    __shared__ __align__(16) unsigned char stage[8192];
    const int tree = blockIdx.x >> 3, kc = blockIdx.x & 7, tid = threadIdx.x;
    for (int e = tid; e < 4096; e += 256) {
        int n = e >> 6, j = e & 63;
        float v = (n < NNODES) ? tw[((size_t)(tree * NNODES + n)) * 512 + kc * 64 + j] : 0.f;
        __nv_bfloat16 h = __float2bfloat16(v);
        int ntile = n >> 3, g = n & 7;
        int kstep = j >> 4, kk = j & 15, tg = (kk >> 1) & 3, regidx = kk >> 3, klo = kk & 1;
        int t = g * 4 + tg;
        uint32_t off = (uint32_t)(((kstep * 4 + (ntile >> 1)) * 32 + t) * 16 +
                                  (ntile & 1) * 8 + regidx * 4 + klo * 2);
        *(__nv_bfloat16*)(stage + off) = h;
    }
    __syncthreads();
    uint4* dst = (uint4*)(g_wf + (size_t)blockIdx.x * 8192);
    const uint4* src = (const uint4*)stage;
    for (int e = tid; e < 512; e += 256) dst[e] = src[e];
}

// ---------- attention (SIMT) ----------
__global__ __launch_bounds__(256) void k_attn(
    const float* __restrict__ x, const float* __restrict__ w1, const float* __restrict__ b1,
    const float* __restrict__ gamma_, const float* __restrict__ beta_,
    const float* __restrict__ mean_, const float* __restrict__ var_,
    const float* __restrict__ w2, const float* __restrict__ b2, const float* __restrict__ resw)
{
    __shared__ __align__(16) char smem[33792];
    float4* xs4 = (float4*)smem; float* xsf = (float*)smem;
    float4* w1s4 = (float4*)(smem + 9216);
    float4* hs4 = (float4*)smem; float* hsf = (float*)smem; float* ls = (float*)smem;
    const int tx = threadIdx.x, row0 = blockIdx.x * 64;
    const int ct = tx & 15, rt = tx >> 4, c0 = ct * 8, r0 = rt * 4;
    float acc[4][8];
#pragma unroll
    for (int i = 0; i < 4; ++i)
#pragma unroll
        for (int j = 0; j < 8; ++j) acc[i][j] = 0.f;
    const float4* x4 = (const float4*)x;
    const float4* w14 = (const float4*)w1;
    for (int kc = 0; kc < 16; ++kc) {
#pragma unroll
        for (int j = 0; j < 2; ++j) {
            int idx = tx + 256 * j, r = idx >> 3, q = idx & 7;
            xs4[r * 9 + q] = x4[(row0 + r) * 128 + kc * 8 + q];
        }
#pragma unroll
        for (int j = 0; j < 4; ++j) {
            int idx = tx + 256 * j, k = idx >> 5, cq = idx & 31;
            w1s4[k * 33 + cq] = w14[(kc * 32 + k) * 32 + cq];
        }
        __syncthreads();
#pragma unroll 4
        for (int kk = 0; kk < 32; ++kk) {
            float4 b0 = w1s4[kk * 33 + ct * 2], b1q = w1s4[kk * 33 + ct * 2 + 1];
#pragma unroll
            for (int i = 0; i < 4; ++i) {
                float a = xsf[(r0 + i) * 36 + kk];
                acc[i][0] += a * b0.x; acc[i][1] += a * b0.y; acc[i][2] += a * b0.z; acc[i][3] += a * b0.w;
                acc[i][4] += a * b1q.x; acc[i][5] += a * b1q.y; acc[i][6] += a * b1q.z; acc[i][7] += a * b1q.w;
            }
        }
        __syncthreads();
    }
    float sc[8], sh[8], bb[8];
#pragma unroll
    for (int j = 0; j < 8; ++j) {
        int c = c0 + j;
        float s = gamma_[c] * rsqrtf(var_[c] + 1e-5f);
        sc[j] = s; sh[j] = beta_[c] - mean_[c] * s; bb[j] = b1[c];
    }
#pragma unroll
    for (int i = 0; i < 4; ++i) {
        float h[8];
#pragma unroll
        for (int j = 0; j < 8; ++j) { float v = fmaxf(acc[i][j] + bb[j], 0.f); h[j] = v * sc[j] + sh[j]; }
        hs4[(r0 + i) * 33 + ct * 2] = make_float4(h[0], h[1], h[2], h[3]);
        hs4[(r0 + i) * 33 + ct * 2 + 1] = make_float4(h[4], h[5], h[6], h[7]);
    }
    __syncthreads();
    const int tt = tx & 15, rt2 = tx >> 4, t0 = tt * 4, r0b = rt2 * 4;
    float a2[4][4];
#pragma unroll
    for (int i = 0; i < 4; ++i)
#pragma unroll
        for (int j = 0; j < 4; ++j) a2[i][j] = b2[t0 + j];
    const float4* w24 = (const float4*)w2;
#pragma unroll 4
    for (int c = 0; c < 128; ++c) {
        float4 wv = __ldg(&w24[c * 16 + tt]);
#pragma unroll
        for (int i = 0; i < 4; ++i) {
            float h = hsf[(r0b + i) * 132 + c];
            a2[i][0] += h * wv.x; a2[i][1] += h * wv.y; a2[i][2] += h * wv.z; a2[i][3] += h * wv.w;
        }
    }
    __syncthreads();
#pragma unroll
    for (int i = 0; i < 4; ++i)
        *(float4*)&ls[(r0b + i) * 68 + t0] = make_float4(a2[i][0], a2[i][1], a2[i][2], a2[i][3]);
    __syncthreads();
    if (tx < 64) {
        int row = row0 + tx;
        const float* lr = ls + tx * 68;
        float m = -1e30f, s = 0.f;
#pragma unroll 4
        for (int t = 0; t < 64; ++t) m = fmaxf(m, lr[t]);
#pragma unroll 4
        for (int t = 0; t < 64; ++t) s += expf(lr[t] - m);
        float inv = 1.f / s;
#pragma unroll 4
        for (int t = 0; t < 64; ++t) g_attn[t * B_TOTAL + row] = expf(lr[t] - m) * inv * (0.3f * resw[t]);
    }
}

// ---------- k_trees: single-pass bf16, paired-B LDS.128, dual-tree epilogue ----------
__global__ __launch_bounds__(512, 1) void k_trees(
    const float* __restrict__ tree_b, const float* __restrict__ tree_temp,
    const float* __restrict__ leaf_values, float* __restrict__ out)
{
    extern __shared__ __align__(16) char smp[];
    const uint32_t sm = smem_u32(smp);
    const int tid = threadIdx.x, lane = tid & 31, wid = tid >> 5;
    const int wt = wid & 1;                 // tree within group
    const int wm = (wid >> 1) & 3;          // M tile (32 rows)
    const int wn = (wid >> 3) & 1;          // N half (4 ni each)
    const int row = tid & 127, part = tid >> 7;   // epilogue: 4 threads/row
    const int rowg = blockIdx.x * 128 + row;
    float* lg = (float*)(smp + OFF_LG);           // [128][LGP], tree tt at col tt*72
    const int miss = g_missing[rowg];

    float pred[NCLS];
#pragma unroll
    for (int c = 0; c < NCLS; ++c) pred[c] = 0.f;

    const unsigned char* xbase = g_xf + (size_t)blockIdx.x * 8 * 16384;

    auto issue = [&](int s) {
        const int grp = s >> 2, kp = s & 3;
        const uint32_t buf = (uint32_t)(s & 1);
        const unsigned char* xsrc = xbase + (size_t)kp * 32768;
        const uint32_t xdst = sm + OFF_X + buf * 32768;
#pragma unroll
        for (int j = 0; j < 4; ++j) {
            int ch = tid + 512 * j;
            CP16(xdst + ch * 16, xsrc + ch * 16);
        }
        const unsigned char* wsrc0 = g_wf + ((size_t)(grp * 2) * 8 + kp * 2) * 8192;
        const uint32_t wdst = sm + OFF_W + buf * 32768;
#pragma unroll
        for (int j = 0; j < 2; ++j) {
            int ch = tid + 512 * j;
            CP16(wdst + ch * 16, wsrc0 + ch * 16);
            CP16(wdst + 16384 + ch * 16, wsrc0 + 8 * 8192 + ch * 16);
        }
        if (kp == 0) {
            const unsigned char* lsrc = (const unsigned char*)leaf_values + (size_t)grp * 5120;
            uint32_t ldst = sm + OFF_LEAF + (uint32_t)(grp & 1) * 5120;
            if (tid < 320) CP16(ldst + tid * 16, lsrc + tid * 16);
        }
    };

    float acc[2][4][4];
#pragma unroll
    for (int mi = 0; mi < 2; ++mi)
#pragma unroll
        for (int ni = 0; ni < 4; ++ni)
#pragma unroll
            for (int q = 0; q < 4; ++q) acc[mi][ni][q] = 0.f;

    issue(0);
    CPCOMMIT();

    for (int s = 0; s < 128; ++s) {
        if (s + 1 < 128) { issue(s + 1); CPCOMMIT(); CPWAIT1(); }
        else CPWAIT0();
        __syncthreads();
        const char* bx = smp + OFF_X + (s & 1) * 32768;
        const char* bw = smp + OFF_W + (s & 1) * 32768 + wt * 16384;
#pragma unroll
        for (int kh = 0; kh < 2; ++kh) {
#pragma unroll
            for (int ks = 0; ks < 4; ++ks) {
                uint4 ah[2];
#pragma unroll
                for (int mi = 0; mi < 2; ++mi)
                    ah[mi] = *(const uint4*)(bx + kh * 16384 +
                        (uint32_t)(((ks * 8 + wm * 2 + mi) * 32 + lane) * 16));
#pragma unroll
                for (int ni2 = 0; ni2 < 2; ++ni2) {
                    uint4 b = *(const uint4*)(bw + kh * 8192 +
                        (uint32_t)(((ks * 4 + wn * 2 + ni2) * 32 + lane) * 16));
#pragma unroll
                    for (int mi = 0; mi < 2; ++mi) {
                        MMA2(acc[mi][ni2 * 2 + 0], ah[mi], b.x, b.y);
                        MMA2(acc[mi][ni2 * 2 + 1], ah[mi], b.z, b.w);
                    }
                }
            }
        }
        __syncthreads();

        if ((s & 3) == 3) {
            const int grp = s >> 2;
            // fragment stores: ALL warps concurrently, tree wt at column wt*72
#pragma unroll
            for (int mi = 0; mi < 2; ++mi)
#pragma unroll
                for (int ni = 0; ni < 4; ++ni) {
                    int r0 = wm * 32 + mi * 16 + (lane >> 2);
                    int c0 = wt * 72 + wn * 32 + ni * 8 + (lane & 3) * 2;
                    *(float2*)&lg[r0 * LGP + c0] = make_float2(acc[mi][ni][0], acc[mi][ni][1]);
                    *(float2*)&lg[(r0 + 8) * LGP + c0] = make_float2(acc[mi][ni][2], acc[mi][ni][3]);
                }
            __syncthreads();
            // sigmoid: both trees in one pass
#pragma unroll
            for (int tt = 0; tt < 2; ++tt) {
                const int t = grp * 2 + tt;
                float invt = 1.f / tree_temp[t];
#pragma unroll
                for (int j = 0; j < 16; ++j) {
                    int n = part * 16 + j;
                    if (n < NNODES) {
                        float z = (lg[row * LGP + tt * 72 + n] + tree_b[t * NNODES + n]) * invt;
                        z = fminf(fmaxf(z, -30.f), 30.f);
                        float d = __fdividef(1.f, 1.f + __expf(-z));
                        lg[row * LGP + tt * 72 + n] = miss ? 0.5f : d;
                    }
                }
            }
            __syncthreads();
            // routing + leaf reduce: both trees
#pragma unroll
            for (int tt = 0; tt < 2; ++tt) {
                const int t = grp * 2 + tt;
                const float* dp = lg + row * LGP + tt * 72;
                const float* lf = (const float*)(smp + OFF_LEAF + (grp & 1) * 5120) + tt * 640;
                float d0 = dp[0], d1 = dp[1], d2 = dp[2];
                float r2[2], r4[4], r8[8];
                r2[0] = d0; r2[1] = 1.f - d0;
                r4[0] = r2[0] * d1; r4[2] = r2[0] - r4[0];
                r4[1] = r2[1] * d2; r4[3] = r2[1] - r4[1];
#pragma unroll
                for (int j = 0; j < 4; ++j) {
                    float d = dp[3 + j];
                    r8[j] = r4[j] * d; r8[j + 4] = r4[j] - r8[j];
                }
                float o[NCLS];
#pragma unroll
                for (int c = 0; c < NCLS; ++c) o[c] = 0.f;
#pragma unroll
                for (int j = 0; j < 8; ++j) {
                    int i = part * 8 + j;
                    float f3 = dp[7 + (i & 7)];   if ((i >> 3) & 1) f3 = 1.f - f3;
                    float f4 = dp[15 + (i & 15)]; if ((i >> 4) & 1) f4 = 1.f - f4;
                    float rr = r8[i & 7] * f3 * f4;
                    float d5 = dp[31 + i];
                    float pL = rr * d5, pR = rr - pL;
                    const float* lL = lf + i * 10;
                    const float* lR = lf + (i + 32) * 10;
#pragma unroll
                    for (int c = 0; c < NCLS; ++c) o[c] += pL * lL[c] + pR * lR[c];
                }
                float at = g_attn[t * B_TOTAL + rowg];
#pragma unroll
                for (int c = 0; c < NCLS; ++c) pred[c] += at * o[c];
            }
            // no barrier: lg not rewritten until after next group's 4 stage barriers
#pragma unroll
            for (int mi = 0; mi < 2; ++mi)
#pragma unroll
                for (int ni = 0; ni < 4; ++ni)
#pragma unroll
                    for (int q = 0; q < 4; ++q) acc[mi][ni][q] = 0.f;
        }
    }

    // combine 4 parts + softmax (barrier first: protect lg from in-flight routing reads)
    __syncthreads();
    float* pred_s = lg;
#pragma unroll
    for (int c = 0; c < NCLS; ++c) pred_s[part * 1280 + row * 10 + c] = pred[c];
    __syncthreads();
    if (tid < 128) {
#pragma unroll
        for (int c = 0; c < NCLS; ++c)
            pred[c] = pred_s[row * 10 + c] + pred_s[1280 + row * 10 + c]
                    + pred_s[2560 + row * 10 + c] + pred_s[3840 + row * 10 + c];
        float m = pred[0];
#pragma unroll
        for (int c = 1; c < NCLS; ++c) m = fmaxf(m, pred[c]);
        float e[NCLS], s = 0.f;
#pragma unroll
        for (int c = 0; c < NCLS; ++c) { e[c] = expf(pred[c] - m); s += e[c]; }
        float inv = 1.f / s;
#pragma unroll
        for (int c = 0; c < NCLS; ++c) out[rowg * 10 + c] = e[c] * inv;
    }
}

// ---------- launcher ----------
extern "C" void kernel_launch(void* const* d_in, const int* in_sizes, int n_in,
                              void* d_out, int out_size) {
    const float* x = (const float*)d_in[0];
    const float* w1 = (const float*)d_in[1];
    const float* b1 = (const float*)d_in[2];
    const float* gm = (const float*)d_in[3];
    const float* bt = (const float*)d_in[4];
    const float* mn = (const float*)d_in[5];
    const float* vr = (const float*)d_in[6];
    const float* w2 = (const float*)d_in[7];
    const float* b2 = (const float*)d_in[8];
    const float* tw = (const float*)d_in[9];
    const float* tb = (const float*)d_in[10];
    const float* tt = (const float*)d_in[11];
    const float* lv = (const float*)d_in[12];
    const float* rw = (const float*)d_in[13];
    cudaFuncSetAttribute(k_trees, cudaFuncAttributeMaxDynamicSharedMemorySize, SMEM_SZ);
    k_prep_x<<<1024, 256>>>(x);
    k_prep_w<<<512, 256>>>(tw);
    k_attn<<<B_TOTAL / 64, 256>>>(x, w1, b1, gm, bt, mn, vr, w2, b2, rw);
    k_trees<<<128, 512, SMEM_SZ>>>(tb, tt, lv, (float*)d_out);
}

// round 13
// speedup vs baseline: 1.1904x; 1.1904x over previous
#include <cuda_runtime.h>
#include <cuda_bf16.h>
#include <cstdint>
#include <math.h>

#define B_TOTAL 16384
#define NTREE 64
#define NNODES 63
#define NCLS 10

__device__ unsigned char g_xf[128 * 8 * 16384]; // [tile128][kc8][hi 16K] A-frag order
__device__ unsigned char g_wf[64 * 8 * 8192];   // [tree][kc8][hi 8K] B-frag, n-tile-paired
__device__ int g_missing[B_TOTAL];
__device__ float g_attn[NTREE * B_TOTAL];

__device__ __forceinline__ uint32_t smem_u32(const void* p) {
    uint32_t a;
    asm("{ .reg .u64 t; cvta.to.shared.u64 t, %1; cvt.u32.u64 %0, t; }" : "=r"(a) : "l"(p));
    return a;
}
#define CP16(s, g) asm volatile("cp.async.cg.shared.global [%0], [%1], 16;" :: "r"(s), "l"(g))
#define CPCOMMIT() asm volatile("cp.async.commit_group;")
#define CPWAIT1() asm volatile("cp.async.wait_group 1;")
#define CPWAIT0() asm volatile("cp.async.wait_group 0;")
#define MMA2(c, a, b0, b1) asm volatile( \
    "mma.sync.aligned.m16n8k16.row.col.f32.bf16.bf16.f32 " \
    "{%0,%1,%2,%3},{%4,%5,%6,%7},{%8,%9},{%0,%1,%2,%3};" \
    : "+f"((c)[0]), "+f"((c)[1]), "+f"((c)[2]), "+f"((c)[3]) \
    : "r"((a).x), "r"((a).y), "r"((a).z), "r"((a).w), "r"(b0), "r"(b1))

// smem layout
#define OFF_X 0u          // 2 x 32768 (2 kc per stage)
#define OFF_W 65536u      // 2 x 32768 (2 trees x 16KB [2 kc])
#define OFF_LG 131072u    // logits 128 x 138 floats (70656) / pred staging
#define OFF_LEAF 201728u  // 2 x 5120
#define SMEM_SZ 211968u
#define LGP 138           // pitch mod 32 = 10 -> 2-way conflicts max
#define TOFF 68           // per-tree column offset

// ---------- prep x: NaN-clean + bf16 hi in A-fragment order ----------
__global__ __launch_bounds__(256) void k_prep_x(const float* __restrict__ x) {
    __shared__ __align__(16) unsigned char stage[16384];
    const int tile = blockIdx.x >> 3, kc = blockIdx.x & 7, tid = threadIdx.x;
    for (int e = tid; e < 8192; e += 256) {
        int r = e >> 6, j = e & 63;
        int row = tile * 128 + r;
        float v = x[row * 512 + kc * 64 + j];
        if (v != v) { v = 0.f; atomicOr(&g_missing[row], 1); }
        __nv_bfloat16 h = __float2bfloat16(v);
        int mtile = r >> 4, row16 = r & 15, g = row16 & 7, half = row16 >> 3;
        int kstep = j >> 4, kk = j & 15, tg = (kk >> 1) & 3, khalf = kk >> 3, klo = kk & 1;
        int t = g * 4 + tg, reg = half + 2 * khalf;
        uint32_t off = (uint32_t)(((kstep * 8 + mtile) * 32 + t) * 16 + reg * 4 + klo * 2);
        *(__nv_bfloat16*)(stage + off) = h;
    }
    __syncthreads();
    uint4* dst = (uint4*)(g_xf + (size_t)blockIdx.x * 16384);
    const uint4* src = (const uint4*)stage;
    for (int e = tid; e < 1024; e += 256) dst[e] = src[e];
}

// ---------- prep w: bf16 hi, B-fragment order with paired n-tiles (16B/lane) ----------
__global__ __launch_bounds__(256) void k_prep_w(const float* __restrict__ tw) {
    __shared__ __align__(16) unsigned char stage[8192];
    const int tree = blockIdx.x >> 3, kc = blockIdx.x & 7, tid = threadIdx.x;
    for (int e = tid; e < 4096; e += 256) {
        int n = e >> 6, j = e & 63;
        float v = (n < NNODES) ? tw[((size_t)(tree * NNODES + n)) * 512 + kc * 64 + j] : 0.f;
        __nv_bfloat16 h = __float2bfloat16(v);
        int ntile = n >> 3, g = n & 7;
        int kstep = j >> 4, kk = j & 15, tg = (kk >> 1) & 3, regidx = kk >> 3, klo = kk & 1;
        int t = g * 4 + tg;
        uint32_t off = (uint32_t)(((kstep * 4 + (ntile >> 1)) * 32 + t) * 16 +
                                  (ntile & 1) * 8 + regidx * 4 + klo * 2);
        *(__nv_bfloat16*)(stage + off) = h;
    }
    __syncthreads();
    uint4* dst = (uint4*)(g_wf + (size_t)blockIdx.x * 8192);
    const uint4* src = (const uint4*)stage;
    for (int e = tid; e < 512; e += 256) dst[e] = src[e];
}

// ---------- attention (SIMT) ----------
__global__ __launch_bounds__(256) void k_attn(
    const float* __restrict__ x, const float* __restrict__ w1, const float* __restrict__ b1,
    const float* __restrict__ gamma_, const float* __restrict__ beta_,
    const float* __restrict__ mean_, const float* __restrict__ var_,
    const float* __restrict__ w2, const float* __restrict__ b2, const float* __restrict__ resw)
{
    __shared__ __align__(16) char smem[33792];
    float4* xs4 = (float4*)smem; float* xsf = (float*)smem;
    float4* w1s4 = (float4*)(smem + 9216);
    float4* hs4 = (float4*)smem; float* hsf = (float*)smem; float* ls = (float*)smem;
    const int tx = threadIdx.x, row0 = blockIdx.x * 64;
    const int ct = tx & 15, rt = tx >> 4, c0 = ct * 8, r0 = rt * 4;
    float acc[4][8];
#pragma unroll
    for (int i = 0; i < 4; ++i)
#pragma unroll
        for (int j = 0; j < 8; ++j) acc[i][j] = 0.f;
    const float4* x4 = (const float4*)x;
    const float4* w14 = (const float4*)w1;
    for (int kc = 0; kc < 16; ++kc) {
#pragma unroll
        for (int j = 0; j < 2; ++j) {
            int idx = tx + 256 * j, r = idx >> 3, q = idx & 7;
            xs4[r * 9 + q] = x4[(row0 + r) * 128 + kc * 8 + q];
        }
#pragma unroll
        for (int j = 0; j < 4; ++j) {
            int idx = tx + 256 * j, k = idx >> 5, cq = idx & 31;
            w1s4[k * 33 + cq] = w14[(kc * 32 + k) * 32 + cq];
        }
        __syncthreads();
#pragma unroll 4
        for (int kk = 0; kk < 32; ++kk) {
            float4 b0 = w1s4[kk * 33 + ct * 2], b1q = w1s4[kk * 33 + ct * 2 + 1];
#pragma unroll
            for (int i = 0; i < 4; ++i) {
                float a = xsf[(r0 + i) * 36 + kk];
                acc[i][0] += a * b0.x; acc[i][1] += a * b0.y; acc[i][2] += a * b0.z; acc[i][3] += a * b0.w;
                acc[i][4] += a * b1q.x; acc[i][5] += a * b1q.y; acc[i][6] += a * b1q.z; acc[i][7] += a * b1q.w;
            }
        }
        __syncthreads();
    }
    float sc[8], sh[8], bb[8];
#pragma unroll
    for (int j = 0; j < 8; ++j) {
        int c = c0 + j;
        float s = gamma_[c] * rsqrtf(var_[c] + 1e-5f);
        sc[j] = s; sh[j] = beta_[c] - mean_[c] * s; bb[j] = b1[c];
    }
#pragma unroll
    for (int i = 0; i < 4; ++i) {
        float h[8];
#pragma unroll
        for (int j = 0; j < 8; ++j) { float v = fmaxf(acc[i][j] + bb[j], 0.f); h[j] = v * sc[j] + sh[j]; }
        hs4[(r0 + i) * 33 + ct * 2] = make_float4(h[0], h[1], h[2], h[3]);
        hs4[(r0 + i) * 33 + ct * 2 + 1] = make_float4(h[4], h[5], h[6], h[7]);
    }
    __syncthreads();
    const int tt = tx & 15, rt2 = tx >> 4, t0 = tt * 4, r0b = rt2 * 4;
    float a2[4][4];
#pragma unroll
    for (int i = 0; i < 4; ++i)
#pragma unroll
        for (int j = 0; j < 4; ++j) a2[i][j] = b2[t0 + j];
    const float4* w24 = (const float4*)w2;
#pragma unroll 4
    for (int c = 0; c < 128; ++c) {
        float4 wv = __ldg(&w24[c * 16 + tt]);
#pragma unroll
        for (int i = 0; i < 4; ++i) {
            float h = hsf[(r0b + i) * 132 + c];
            a2[i][0] += h * wv.x; a2[i][1] += h * wv.y; a2[i][2] += h * wv.z; a2[i][3] += h * wv.w;
        }
    }
    __syncthreads();
#pragma unroll
    for (int i = 0; i < 4; ++i)
        *(float4*)&ls[(r0b + i) * 68 + t0] = make_float4(a2[i][0], a2[i][1], a2[i][2], a2[i][3]);
    __syncthreads();
    if (tx < 64) {
        int row = row0 + tx;
        const float* lr = ls + tx * 68;
        float m = -1e30f, s = 0.f;
#pragma unroll 4
        for (int t = 0; t < 64; ++t) m = fmaxf(m, lr[t]);
#pragma unroll 4
        for (int t = 0; t < 64; ++t) s += expf(lr[t] - m);
        float inv = 1.f / s;
#pragma unroll 4
        for (int t = 0; t < 64; ++t) g_attn[t * B_TOTAL + row] = expf(lr[t] - m) * inv * (0.3f * resw[t]);
    }
}

// ---------- k_trees: single-pass bf16, dual-tree epilogue, 2-way-conflict pitch ----------
__global__ __launch_bounds__(512, 1) void k_trees(
    const float* __restrict__ tree_b, const float* __restrict__ tree_temp,
    const float* __restrict__ leaf_values, float* __restrict__ out)
{
    extern __shared__ __align__(16) char smp[];
    const uint32_t sm = smem_u32(smp);
    const int tid = threadIdx.x, lane = tid & 31, wid = tid >> 5;
    const int wt = wid & 1;                 // tree within group
    const int wm = (wid >> 1) & 3;          // M tile (32 rows)
    const int wn = (wid >> 3) & 1;          // N half (4 ni each)
    const int row = tid & 127, part = tid >> 7;   // epilogue: 4 threads/row
    const int rowg = blockIdx.x * 128 + row;
    float* lg = (float*)(smp + OFF_LG);           // [128][LGP], tree tt at col tt*TOFF
    const int miss = g_missing[rowg];

    float pred[NCLS];
#pragma unroll
    for (int c = 0; c < NCLS; ++c) pred[c] = 0.f;

    const unsigned char* xbase = g_xf + (size_t)blockIdx.x * 8 * 16384;

    auto issue = [&](int s) {
        const int grp = s >> 2, kp = s & 3;
        const uint32_t buf = (uint32_t)(s & 1);
        const unsigned char* xsrc = xbase + (size_t)kp * 32768;
        const uint32_t xdst = sm + OFF_X + buf * 32768;
#pragma unroll
        for (int j = 0; j < 4; ++j) {
            int ch = tid + 512 * j;
            CP16(xdst + ch * 16, xsrc + ch * 16);
        }
        const unsigned char* wsrc0 = g_wf + ((size_t)(grp * 2) * 8 + kp * 2) * 8192;
        const uint32_t wdst = sm + OFF_W + buf * 32768;
#pragma unroll
        for (int j = 0; j < 2; ++j) {
            int ch = tid + 512 * j;
            CP16(wdst + ch * 16, wsrc0 + ch * 16);
            CP16(wdst + 16384 + ch * 16, wsrc0 + 8 * 8192 + ch * 16);
        }
        if (kp == 0) {
            const unsigned char* lsrc = (const unsigned char*)leaf_values + (size_t)grp * 5120;
            uint32_t ldst = sm + OFF_LEAF + (uint32_t)(grp & 1) * 5120;
            if (tid < 320) CP16(ldst + tid * 16, lsrc + tid * 16);
        }
    };

    float acc[2][4][4];
#pragma unroll
    for (int mi = 0; mi < 2; ++mi)
#pragma unroll
        for (int ni = 0; ni < 4; ++ni)
#pragma unroll
            for (int q = 0; q < 4; ++q) acc[mi][ni][q] = 0.f;

    issue(0);
    CPCOMMIT();

    for (int s = 0; s < 128; ++s) {
        if (s + 1 < 128) { issue(s + 1); CPCOMMIT(); CPWAIT1(); }
        else CPWAIT0();
        __syncthreads();
        const char* bx = smp + OFF_X + (s & 1) * 32768;
        const char* bw = smp + OFF_W + (s & 1) * 32768 + wt * 16384;
#pragma unroll
        for (int kh = 0; kh < 2; ++kh) {
#pragma unroll
            for (int ks = 0; ks < 4; ++ks) {
                uint4 ah[2];
#pragma unroll
                for (int mi = 0; mi < 2; ++mi)
                    ah[mi] = *(const uint4*)(bx + kh * 16384 +
                        (uint32_t)(((ks * 8 + wm * 2 + mi) * 32 + lane) * 16));
#pragma unroll
                for (int ni2 = 0; ni2 < 2; ++ni2) {
                    uint4 b = *(const uint4*)(bw + kh * 8192 +
                        (uint32_t)(((ks * 4 + wn * 2 + ni2) * 32 + lane) * 16));
#pragma unroll
                    for (int mi = 0; mi < 2; ++mi) {
                        MMA2(acc[mi][ni2 * 2 + 0], ah[mi], b.x, b.y);
                        MMA2(acc[mi][ni2 * 2 + 1], ah[mi], b.z, b.w);
                    }
                }
            }
        }
        __syncthreads();

        if ((s & 3) == 3) {
            const int grp = s >> 2;
            // fragment stores: ALL warps concurrently, tree wt at column wt*TOFF
#pragma unroll
            for (int mi = 0; mi < 2; ++mi)
#pragma unroll
                for (int ni = 0; ni < 4; ++ni) {
                    int r0 = wm * 32 + mi * 16 + (lane >> 2);
                    int c0 = wt * TOFF + wn * 32 + ni * 8 + (lane & 3) * 2;
                    *(float2*)&lg[r0 * LGP + c0] = make_float2(acc[mi][ni][0], acc[mi][ni][1]);
                    *(float2*)&lg[(r0 + 8) * LGP + c0] = make_float2(acc[mi][ni][2], acc[mi][ni][3]);
                }
            __syncthreads();
            // sigmoid: both trees in one pass
#pragma unroll
            for (int tt = 0; tt < 2; ++tt) {
                const int t = grp * 2 + tt;
                float invt = 1.f / tree_temp[t];
#pragma unroll
                for (int j = 0; j < 16; ++j) {
                    int n = part * 16 + j;
                    if (n < NNODES) {
                        float z = (lg[row * LGP + tt * TOFF + n] + tree_b[t * NNODES + n]) * invt;
                        z = fminf(fmaxf(z, -30.f), 30.f);
                        float d = __fdividef(1.f, 1.f + __expf(-z));
                        lg[row * LGP + tt * TOFF + n] = miss ? 0.5f : d;
                    }
                }
            }
            __syncthreads();
            // routing + leaf reduce: both trees
#pragma unroll
            for (int tt = 0; tt < 2; ++tt) {
                const int t = grp * 2 + tt;
                const float* dp = lg + row * LGP + tt * TOFF;
                const float* lf = (const float*)(smp + OFF_LEAF + (grp & 1) * 5120) + tt * 640;
                float d0 = dp[0], d1 = dp[1], d2 = dp[2];
                float r2[2], r4[4], r8[8];
                r2[0] = d0; r2[1] = 1.f - d0;
                r4[0] = r2[0] * d1; r4[2] = r2[0] - r4[0];
                r4[1] = r2[1] * d2; r4[3] = r2[1] - r4[1];
#pragma unroll
                for (int j = 0; j < 4; ++j) {
                    float d = dp[3 + j];
                    r8[j] = r4[j] * d; r8[j + 4] = r4[j] - r8[j];
                }
                float o[NCLS];
#pragma unroll
                for (int c = 0; c < NCLS; ++c) o[c] = 0.f;
#pragma unroll
                for (int j = 0; j < 8; ++j) {
                    int i = part * 8 + j;
                    float f3 = dp[7 + (i & 7)];   if ((i >> 3) & 1) f3 = 1.f - f3;
                    float f4 = dp[15 + (i & 15)]; if ((i >> 4) & 1) f4 = 1.f - f4;
                    float rr = r8[i & 7] * f3 * f4;
                    float d5 = dp[31 + i];
                    float pL = rr * d5, pR = rr - pL;
                    const float* lL = lf + i * 10;
                    const float* lR = lf + (i + 32) * 10;
#pragma unroll
                    for (int c = 0; c < NCLS; ++c) o[c] += pL * lL[c] + pR * lR[c];
                }
                float at = g_attn[t * B_TOTAL + rowg];
#pragma unroll
                for (int c = 0; c < NCLS; ++c) pred[c] += at * o[c];
            }
            // no barrier: lg not rewritten until after next group's 4 stage barriers
#pragma unroll
            for (int mi = 0; mi < 2; ++mi)
#pragma unroll
                for (int ni = 0; ni < 4; ++ni)
#pragma unroll
                    for (int q = 0; q < 4; ++q) acc[mi][ni][q] = 0.f;
        }
    }

    // combine 4 parts + softmax (barrier first: protect lg from in-flight routing reads)
    __syncthreads();
    float* pred_s = lg;
#pragma unroll
    for (int c = 0; c < NCLS; ++c) pred_s[part * 1280 + row * 10 + c] = pred[c];
    __syncthreads();
    if (tid < 128) {
#pragma unroll
        for (int c = 0; c < NCLS; ++c)
            pred[c] = pred_s[row * 10 + c] + pred_s[1280 + row * 10 + c]
                    + pred_s[2560 + row * 10 + c] + pred_s[3840 + row * 10 + c];
        float m = pred[0];
#pragma unroll
        for (int c = 1; c < NCLS; ++c) m = fmaxf(m, pred[c]);
        float e[NCLS], s = 0.f;
#pragma unroll
        for (int c = 0; c < NCLS; ++c) { e[c] = expf(pred[c] - m); s += e[c]; }
        float inv = 1.f / s;
#pragma unroll
        for (int c = 0; c < NCLS; ++c) out[rowg * 10 + c] = e[c] * inv;
    }
}

// ---------- launcher ----------
extern "C" void kernel_launch(void* const* d_in, const int* in_sizes, int n_in,
                              void* d_out, int out_size) {
    const float* x = (const float*)d_in[0];
    const float* w1 = (const float*)d_in[1];
    const float* b1 = (const float*)d_in[2];
    const float* gm = (const float*)d_in[3];
    const float* bt = (const float*)d_in[4];
    const float* mn = (const float*)d_in[5];
    const float* vr = (const float*)d_in[6];
    const float* w2 = (const float*)d_in[7];
    const float* b2 = (const float*)d_in[8];
    const float* tw = (const float*)d_in[9];
    const float* tb = (const float*)d_in[10];
    const float* tt = (const float*)d_in[11];
    const float* lv = (const float*)d_in[12];
    const float* rw = (const float*)d_in[13];
    cudaFuncSetAttribute(k_trees, cudaFuncAttributeMaxDynamicSharedMemorySize, SMEM_SZ);
    k_prep_x<<<1024, 256>>>(x);
    k_prep_w<<<512, 256>>>(tw);
    k_attn<<<B_TOTAL / 64, 256>>>(x, w1, b1, gm, bt, mn, vr, w2, b2, rw);
    k_trees<<<128, 512, SMEM_SZ>>>(tb, tt, lv, (float*)d_out);
}

// round 14
// speedup vs baseline: 1.2432x; 1.0443x over previous
#include <cuda_runtime.h>
#include <cuda_bf16.h>
#include <cstdint>
#include <math.h>

#define B_TOTAL 16384
#define NTREE 64
#define NNODES 63
#define NCLS 10

__device__ unsigned char g_xf[128 * 8 * 16384]; // [tile128][kc8][hi 16K] A-frag order
__device__ unsigned char g_wf[64 * 8 * 8192];   // [tree][kc8][hi 8K] B-frag, n-tile-paired
__device__ int g_missing[B_TOTAL];
__device__ float g_attn[NTREE * B_TOTAL];

__device__ __forceinline__ uint32_t smem_u32(const void* p) {
    uint32_t a;
    asm("{ .reg .u64 t; cvta.to.shared.u64 t, %1; cvt.u32.u64 %0, t; }" : "=r"(a) : "l"(p));
    return a;
}
#define CP16(s, g) asm volatile("cp.async.cg.shared.global [%0], [%1], 16;" :: "r"(s), "l"(g))
#define CPCOMMIT() asm volatile("cp.async.commit_group;")
#define CPWAIT1() asm volatile("cp.async.wait_group 1;")
#define CPWAIT0() asm volatile("cp.async.wait_group 0;")
#define MMA2(c, a, b0, b1) asm volatile( \
    "mma.sync.aligned.m16n8k16.row.col.f32.bf16.bf16.f32 " \
    "{%0,%1,%2,%3},{%4,%5,%6,%7},{%8,%9},{%0,%1,%2,%3};" \
    : "+f"((c)[0]), "+f"((c)[1]), "+f"((c)[2]), "+f"((c)[3]) \
    : "r"((a).x), "r"((a).y), "r"((a).z), "r"((a).w), "r"(b0), "r"(b1))

// smem layout (per 64-row CTA; 2 CTAs/SM)
#define OFF_X 0u          // 2 x 8192 (1 kc per stage, 64 rows)
#define OFF_W 16384u      // 2 x 16384 (2 trees x 8KB)
#define OFF_LG 49152u     // logits 64 x 138 floats (35328) / pred staging
#define OFF_LEAF 84480u   // 2 x 5120
#define SMEM_SZ 94720u
#define LGP 138           // pitch mod 32 = 10 -> 2-way conflicts max
#define TOFF 68           // per-tree column offset

// ---------- prep x: NaN-clean + bf16 hi in A-fragment order ----------
__global__ __launch_bounds__(256) void k_prep_x(const float* __restrict__ x) {
    __shared__ __align__(16) unsigned char stage[16384];
    const int tile = blockIdx.x >> 3, kc = blockIdx.x & 7, tid = threadIdx.x;
    for (int e = tid; e < 8192; e += 256) {
        int r = e >> 6, j = e & 63;
        int row = tile * 128 + r;
        float v = x[row * 512 + kc * 64 + j];
        if (v != v) { v = 0.f; atomicOr(&g_missing[row], 1); }
        __nv_bfloat16 h = __float2bfloat16(v);
        int mtile = r >> 4, row16 = r & 15, g = row16 & 7, half = row16 >> 3;
        int kstep = j >> 4, kk = j & 15, tg = (kk >> 1) & 3, khalf = kk >> 3, klo = kk & 1;
        int t = g * 4 + tg, reg = half + 2 * khalf;
        uint32_t off = (uint32_t)(((kstep * 8 + mtile) * 32 + t) * 16 + reg * 4 + klo * 2);
        *(__nv_bfloat16*)(stage + off) = h;
    }
    __syncthreads();
    uint4* dst = (uint4*)(g_xf + (size_t)blockIdx.x * 16384);
    const uint4* src = (const uint4*)stage;
    for (int e = tid; e < 1024; e += 256) dst[e] = src[e];
}

// ---------- prep w: bf16 hi, B-fragment order with paired n-tiles (16B/lane) ----------
__global__ __launch_bounds__(256) void k_prep_w(const float* __restrict__ tw) {
    __shared__ __align__(16) unsigned char stage[8192];
    const int tree = blockIdx.x >> 3, kc = blockIdx.x & 7, tid = threadIdx.x;
    for (int e = tid; e < 4096; e += 256) {
        int n = e >> 6, j = e & 63;
        float v = (n < NNODES) ? tw[((size_t)(tree * NNODES + n)) * 512 + kc * 64 + j] : 0.f;
        __nv_bfloat16 h = __float2bfloat16(v);
        int ntile = n >> 3, g = n & 7;
        int kstep = j >> 4, kk = j & 15, tg = (kk >> 1) & 3, regidx = kk >> 3, klo = kk & 1;
        int t = g * 4 + tg;
        uint32_t off = (uint32_t)(((kstep * 4 + (ntile >> 1)) * 32 + t) * 16 +
                                  (ntile & 1) * 8 + regidx * 4 + klo * 2);
        *(__nv_bfloat16*)(stage + off) = h;
    }
    __syncthreads();
    uint4* dst = (uint4*)(g_wf + (size_t)blockIdx.x * 8192);
    const uint4* src = (const uint4*)stage;
    for (int e = tid; e < 512; e += 256) dst[e] = src[e];
}

// ---------- attention (SIMT) ----------
__global__ __launch_bounds__(256) void k_attn(
    const float* __restrict__ x, const float* __restrict__ w1, const float* __restrict__ b1,
    const float* __restrict__ gamma_, const float* __restrict__ beta_,
    const float* __restrict__ mean_, const float* __restrict__ var_,
    const float* __restrict__ w2, const float* __restrict__ b2, const float* __restrict__ resw)
{
    __shared__ __align__(16) char smem[33792];
    float4* xs4 = (float4*)smem; float* xsf = (float*)smem;
    float4* w1s4 = (float4*)(smem + 9216);
    float4* hs4 = (float4*)smem; float* hsf = (float*)smem; float* ls = (float*)smem;
    const int tx = threadIdx.x, row0 = blockIdx.x * 64;
    const int ct = tx & 15, rt = tx >> 4, c0 = ct * 8, r0 = rt * 4;
    float acc[4][8];
#pragma unroll
    for (int i = 0; i < 4; ++i)
#pragma unroll
        for (int j = 0; j < 8; ++j) acc[i][j] = 0.f;
    const float4* x4 = (const float4*)x;
    const float4* w14 = (const float4*)w1;
    for (int kc = 0; kc < 16; ++kc) {
#pragma unroll
        for (int j = 0; j < 2; ++j) {
            int idx = tx + 256 * j, r = idx >> 3, q = idx & 7;
            xs4[r * 9 + q] = x4[(row0 + r) * 128 + kc * 8 + q];
        }
#pragma unroll
        for (int j = 0; j < 4; ++j) {
            int idx = tx + 256 * j, k = idx >> 5, cq = idx & 31;
            w1s4[k * 33 + cq] = w14[(kc * 32 + k) * 32 + cq];
        }
        __syncthreads();
#pragma unroll 4
        for (int kk = 0; kk < 32; ++kk) {
            float4 b0 = w1s4[kk * 33 + ct * 2], b1q = w1s4[kk * 33 + ct * 2 + 1];
#pragma unroll
            for (int i = 0; i < 4; ++i) {
                float a = xsf[(r0 + i) * 36 + kk];
                acc[i][0] += a * b0.x; acc[i][1] += a * b0.y; acc[i][2] += a * b0.z; acc[i][3] += a * b0.w;
                acc[i][4] += a * b1q.x; acc[i][5] += a * b1q.y; acc[i][6] += a * b1q.z; acc[i][7] += a * b1q.w;
            }
        }
        __syncthreads();
    }
    float sc[8], sh[8], bb[8];
#pragma unroll
    for (int j = 0; j < 8; ++j) {
        int c = c0 + j;
        float s = gamma_[c] * rsqrtf(var_[c] + 1e-5f);
        sc[j] = s; sh[j] = beta_[c] - mean_[c] * s; bb[j] = b1[c];
    }
#pragma unroll
    for (int i = 0; i < 4; ++i) {
        float h[8];
#pragma unroll
        for (int j = 0; j < 8; ++j) { float v = fmaxf(acc[i][j] + bb[j], 0.f); h[j] = v * sc[j] + sh[j]; }
        hs4[(r0 + i) * 33 + ct * 2] = make_float4(h[0], h[1], h[2], h[3]);
        hs4[(r0 + i) * 33 + ct * 2 + 1] = make_float4(h[4], h[5], h[6], h[7]);
    }
    __syncthreads();
    const int tt = tx & 15, rt2 = tx >> 4, t0 = tt * 4, r0b = rt2 * 4;
    float a2[4][4];
#pragma unroll
    for (int i = 0; i < 4; ++i)
#pragma unroll
        for (int j = 0; j < 4; ++j) a2[i][j] = b2[t0 + j];
    const float4* w24 = (const float4*)w2;
#pragma unroll 4
    for (int c = 0; c < 128; ++c) {
        float4 wv = __ldg(&w24[c * 16 + tt]);
#pragma unroll
        for (int i = 0; i < 4; ++i) {
            float h = hsf[(r0b + i) * 132 + c];
            a2[i][0] += h * wv.x; a2[i][1] += h * wv.y; a2[i][2] += h * wv.z; a2[i][3] += h * wv.w;
        }
    }
    __syncthreads();
#pragma unroll
    for (int i = 0; i < 4; ++i)
        *(float4*)&ls[(r0b + i) * 68 + t0] = make_float4(a2[i][0], a2[i][1], a2[i][2], a2[i][3]);
    __syncthreads();
    if (tx < 64) {
        int row = row0 + tx;
        const float* lr = ls + tx * 68;
        float m = -1e30f, s = 0.f;
#pragma unroll 4
        for (int t = 0; t < 64; ++t) m = fmaxf(m, lr[t]);
#pragma unroll 4
        for (int t = 0; t < 64; ++t) s += expf(lr[t] - m);
        float inv = 1.f / s;
#pragma unroll 4
        for (int t = 0; t < 64; ++t) g_attn[t * B_TOTAL + row] = expf(lr[t] - m) * inv * (0.3f * resw[t]);
    }
}

// ---------- k_trees: 256 thr / 64 rows / 2 CTAs per SM (epilogue-mainloop overlap) ----------
__global__ __launch_bounds__(256, 2) void k_trees(
    const float* __restrict__ tree_b, const float* __restrict__ tree_temp,
    const float* __restrict__ leaf_values, float* __restrict__ out)
{
    extern __shared__ __align__(16) char smp[];
    const uint32_t sm = smem_u32(smp);
    const int tid = threadIdx.x, lane = tid & 31, wid = tid >> 5;
    const int wt = wid & 1;                 // tree within group
    const int wm = (wid >> 1) & 1;          // M tile (32 rows of 64)
    const int wn = (wid >> 2) & 1;          // N half (4 ni each)
    const int row = tid & 63, part = tid >> 6;    // epilogue: 4 threads/row
    const int rowg = blockIdx.x * 64 + row;
    const int chalf = blockIdx.x & 1;             // which 64-row half of the 128-row x-tile
    float* lg = (float*)(smp + OFF_LG);           // [64][LGP], tree tt at col tt*TOFF
    const int miss = g_missing[rowg];

    float pred[NCLS];
#pragma unroll
    for (int c = 0; c < NCLS; ++c) pred[c] = 0.f;

    const unsigned char* xbase = g_xf + (size_t)(blockIdx.x >> 1) * 8 * 16384;

    auto issue = [&](int s) {
        const int grp = s >> 3, kc = s & 7;
        const uint32_t buf = (uint32_t)(s & 1);
        // X: this CTA's 64-row half of the kc block: 4 chunks (kstep) x 2KB
        const unsigned char* xsrc = xbase + (size_t)kc * 16384;
        const uint32_t xdst = sm + OFF_X + buf * 8192;
#pragma unroll
        for (int j = 0; j < 2; ++j) {
            int ch = tid + 256 * j;            // 0..511
            int kstep = ch >> 7, rem = ch & 127;
            CP16(xdst + ch * 16, xsrc + (uint32_t)((kstep * 8 + 4 * chalf) * 512 + rem * 16));
        }
        // W: 2 trees x 8KB
        const unsigned char* wsrc0 = g_wf + ((size_t)(grp * 2) * 8 + kc) * 8192;
        const uint32_t wdst = sm + OFF_W + buf * 16384;
#pragma unroll
        for (int j = 0; j < 2; ++j) {
            int ch = tid + 256 * j;            // 0..511 per tree
            CP16(wdst + ch * 16, wsrc0 + ch * 16);
            CP16(wdst + 8192 + ch * 16, wsrc0 + 8 * 8192 + ch * 16);
        }
        if (kc == 0) {
            const unsigned char* lsrc = (const unsigned char*)leaf_values + (size_t)grp * 5120;
            uint32_t ldst = sm + OFF_LEAF + (uint32_t)(grp & 1) * 5120;
            CP16(ldst + tid * 16, lsrc + tid * 16);
            if (tid < 64) CP16(ldst + (tid + 256) * 16, lsrc + (tid + 256) * 16);
        }
    };

    float acc[2][4][4];
#pragma unroll
    for (int mi = 0; mi < 2; ++mi)
#pragma unroll
        for (int ni = 0; ni < 4; ++ni)
#pragma unroll
            for (int q = 0; q < 4; ++q) acc[mi][ni][q] = 0.f;

    issue(0);
    CPCOMMIT();

    for (int s = 0; s < 256; ++s) {
        if (s + 1 < 256) { issue(s + 1); CPCOMMIT(); CPWAIT1(); }
        else CPWAIT0();
        __syncthreads();
        const char* bx = smp + OFF_X + (s & 1) * 8192;
        const char* bw = smp + OFF_W + (s & 1) * 16384 + wt * 8192;
#pragma unroll
        for (int ks = 0; ks < 4; ++ks) {
            uint4 ah[2];
#pragma unroll
            for (int mi = 0; mi < 2; ++mi)
                ah[mi] = *(const uint4*)(bx +
                    (uint32_t)(((ks * 4 + wm * 2 + mi) * 32 + lane) * 16));
#pragma unroll
            for (int ni2 = 0; ni2 < 2; ++ni2) {
                uint4 b = *(const uint4*)(bw +
                    (uint32_t)(((ks * 4 + wn * 2 + ni2) * 32 + lane) * 16));
#pragma unroll
                for (int mi = 0; mi < 2; ++mi) {
                    MMA2(acc[mi][ni2 * 2 + 0], ah[mi], b.x, b.y);
                    MMA2(acc[mi][ni2 * 2 + 1], ah[mi], b.z, b.w);
                }
            }
        }
        __syncthreads();

        if ((s & 7) == 7) {
            const int grp = s >> 3;
            // fragment stores: all warps concurrently, tree wt at column wt*TOFF
#pragma unroll
            for (int mi = 0; mi < 2; ++mi)
#pragma unroll
                for (int ni = 0; ni < 4; ++ni) {
                    int r0 = wm * 32 + mi * 16 + (lane >> 2);
                    int c0 = wt * TOFF + wn * 32 + ni * 8 + (lane & 3) * 2;
                    *(float2*)&lg[r0 * LGP + c0] = make_float2(acc[mi][ni][0], acc[mi][ni][1]);
                    *(float2*)&lg[(r0 + 8) * LGP + c0] = make_float2(acc[mi][ni][2], acc[mi][ni][3]);
                }
            __syncthreads();
            // sigmoid: both trees in one pass
#pragma unroll
            for (int tt = 0; tt < 2; ++tt) {
                const int t = grp * 2 + tt;
                float invt = 1.f / tree_temp[t];
#pragma unroll
                for (int j = 0; j < 16; ++j) {
                    int n = part * 16 + j;
                    if (n < NNODES) {
                        float z = (lg[row * LGP + tt * TOFF + n] + tree_b[t * NNODES + n]) * invt;
                        z = fminf(fmaxf(z, -30.f), 30.f);
                        float d = __fdividef(1.f, 1.f + __expf(-z));
                        lg[row * LGP + tt * TOFF + n] = miss ? 0.5f : d;
                    }
                }
            }
            __syncthreads();
            // routing + leaf reduce: both trees
#pragma unroll
            for (int tt = 0; tt < 2; ++tt) {
                const int t = grp * 2 + tt;
                const float* dp = lg + row * LGP + tt * TOFF;
                const float* lf = (const float*)(smp + OFF_LEAF + (grp & 1) * 5120) + tt * 640;
                float d0 = dp[0], d1 = dp[1], d2 = dp[2];
                float r2[2], r4[4], r8[8];
                r2[0] = d0; r2[1] = 1.f - d0;
                r4[0] = r2[0] * d1; r4[2] = r2[0] - r4[0];
                r4[1] = r2[1] * d2; r4[3] = r2[1] - r4[1];
#pragma unroll
                for (int j = 0; j < 4; ++j) {
                    float d = dp[3 + j];
                    r8[j] = r4[j] * d; r8[j + 4] = r4[j] - r8[j];
                }
                float o[NCLS];
#pragma unroll
                for (int c = 0; c < NCLS; ++c) o[c] = 0.f;
#pragma unroll
                for (int j = 0; j < 8; ++j) {
                    int i = part * 8 + j;
                    float f3 = dp[7 + (i & 7)];   if ((i >> 3) & 1) f3 = 1.f - f3;
                    float f4 = dp[15 + (i & 15)]; if ((i >> 4) & 1) f4 = 1.f - f4;
                    float rr = r8[i & 7] * f3 * f4;
                    float d5 = dp[31 + i];
                    float pL = rr * d5, pR = rr - pL;
                    const float* lL = lf + i * 10;
                    const float* lR = lf + (i + 32) * 10;
#pragma unroll
                    for (int c = 0; c < NCLS; ++c) o[c] += pL * lL[c] + pR * lR[c];
                }
                float at = g_attn[t * B_TOTAL + rowg];
#pragma unroll
                for (int c = 0; c < NCLS; ++c) pred[c] += at * o[c];
            }
            // no barrier: lg not rewritten until after next group's stage barriers
#pragma unroll
            for (int mi = 0; mi < 2; ++mi)
#pragma unroll
                for (int ni = 0; ni < 4; ++ni)
#pragma unroll
                    for (int q = 0; q < 4; ++q) acc[mi][ni][q] = 0.f;
        }
    }

    // combine 4 parts + softmax
    __syncthreads();
    float* pred_s = lg;
#pragma unroll
    for (int c = 0; c < NCLS; ++c) pred_s[part * 640 + row * 10 + c] = pred[c];
    __syncthreads();
    if (tid < 64) {
#pragma unroll
        for (int c = 0; c < NCLS; ++c)
            pred[c] = pred_s[row * 10 + c] + pred_s[640 + row * 10 + c]
                    + pred_s[1280 + row * 10 + c] + pred_s[1920 + row * 10 + c];
        float m = pred[0];
#pragma unroll
        for (int c = 1; c < NCLS; ++c) m = fmaxf(m, pred[c]);
        float e[NCLS], s = 0.f;
#pragma unroll
        for (int c = 0; c < NCLS; ++c) { e[c] = expf(pred[c] - m); s += e[c]; }
        float inv = 1.f / s;
#pragma unroll
        for (int c = 0; c < NCLS; ++c) out[rowg * 10 + c] = e[c] * inv;
    }
}

// ---------- launcher ----------
extern "C" void kernel_launch(void* const* d_in, const int* in_sizes, int n_in,
                              void* d_out, int out_size) {
    const float* x = (const float*)d_in[0];
    const float* w1 = (const float*)d_in[1];
    const float* b1 = (const float*)d_in[2];
    const float* gm = (const float*)d_in[3];
    const float* bt = (const float*)d_in[4];
    const float* mn = (const float*)d_in[5];
    const float* vr = (const float*)d_in[6];
    const float* w2 = (const float*)d_in[7];
    const float* b2 = (const float*)d_in[8];
    const float* tw = (const float*)d_in[9];
    const float* tb = (const float*)d_in[10];
    const float* tt = (const float*)d_in[11];
    const float* lv = (const float*)d_in[12];
    const float* rw = (const float*)d_in[13];
    cudaFuncSetAttribute(k_trees, cudaFuncAttributeMaxDynamicSharedMemorySize, SMEM_SZ);
    k_prep_x<<<1024, 256>>>(x);
    k_prep_w<<<512, 256>>>(tw);
    k_attn<<<B_TOTAL / 64, 256>>>(x, w1, b1, gm, bt, mn, vr, w2, b2, rw);
    k_trees<<<256, 256, SMEM_SZ>>>(tb, tt, lv, (float*)d_out);
}

// round 16
// speedup vs baseline: 1.3980x; 1.1245x over previous
#include <cuda_runtime.h>
#include <cuda_bf16.h>
#include <cstdint>
#include <math.h>

#define B_TOTAL 16384
#define NTREE 64
#define NNODES 63
#define NCLS 10

__device__ unsigned char g_xf[128 * 8 * 16384]; // x hi, A-frag order
__device__ unsigned char g_xl[128 * 8 * 16384]; // x lo, A-frag order
__device__ unsigned char g_wf[64 * 8 * 8192];   // tree_w hi, B-frag n-paired
__device__ unsigned char g_w1f[8 * 32768];      // W1 [kc][hi16K|lo16K], B-frag n-paired
__device__ int g_missing[B_TOTAL];
__device__ float g_attn[NTREE * B_TOTAL];

__device__ __forceinline__ uint32_t smem_u32(const void* p) {
    uint32_t a;
    asm("{ .reg .u64 t; cvta.to.shared.u64 t, %1; cvt.u32.u64 %0, t; }" : "=r"(a) : "l"(p));
    return a;
}
#define CP16(s, g) asm volatile("cp.async.cg.shared.global [%0], [%1], 16;" :: "r"(s), "l"(g))
#define CPCOMMIT() asm volatile("cp.async.commit_group;")
#define CPWAIT1() asm volatile("cp.async.wait_group 1;")
#define CPWAIT0() asm volatile("cp.async.wait_group 0;")
#define MMA2(c, a, b0, b1) asm volatile( \
    "mma.sync.aligned.m16n8k16.row.col.f32.bf16.bf16.f32 " \
    "{%0,%1,%2,%3},{%4,%5,%6,%7},{%8,%9},{%0,%1,%2,%3};" \
    : "+f"((c)[0]), "+f"((c)[1]), "+f"((c)[2]), "+f"((c)[3]) \
    : "r"((a).x), "r"((a).y), "r"((a).z), "r"((a).w), "r"(b0), "r"(b1))

// k_trees smem
#define OFF_X 0u
#define OFF_W 16384u
#define OFF_LG 49152u
#define OFF_LEAF 84480u
#define SMEM_SZ 94720u
#define LGP 138
#define TOFF 68
// k_attn smem
#define AOFF_X 0u         // 2 x 32768 (hi16K|lo16K)
#define AOFF_W 65536u     // 2 x 32768
#define AOFF_H 131072u    // h: 128 x 132 f32 (67584); reused for logits
#define ATTN_SMEM 198656u

// ---------- prep x: NaN-clean + bf16 hi/lo in A-fragment order ----------
__global__ __launch_bounds__(256) void k_prep_x(const float* __restrict__ x) {
    __shared__ __align__(16) unsigned char stage[32768];
    const int tile = blockIdx.x >> 3, kc = blockIdx.x & 7, tid = threadIdx.x;
    for (int e = tid; e < 8192; e += 256) {
        int r = e >> 6, j = e & 63;
        int row = tile * 128 + r;
        float v = x[row * 512 + kc * 64 + j];
        if (v != v) { v = 0.f; atomicOr(&g_missing[row], 1); }
        __nv_bfloat16 h = __float2bfloat16(v);
        __nv_bfloat16 l = __float2bfloat16(v - __bfloat162float(h));
        int mtile = r >> 4, row16 = r & 15, g = row16 & 7, half = row16 >> 3;
        int kstep = j >> 4, kk = j & 15, tg = (kk >> 1) & 3, khalf = kk >> 3, klo = kk & 1;
        int t = g * 4 + tg, reg = half + 2 * khalf;
        uint32_t off = (uint32_t)(((kstep * 8 + mtile) * 32 + t) * 16 + reg * 4 + klo * 2);
        *(__nv_bfloat16*)(stage + off) = h;
        *(__nv_bfloat16*)(stage + 16384 + off) = l;
    }
    __syncthreads();
    uint4* d0 = (uint4*)(g_xf + (size_t)blockIdx.x * 16384);
    uint4* d1 = (uint4*)(g_xl + (size_t)blockIdx.x * 16384);
    const uint4* src = (const uint4*)stage;
    for (int e = tid; e < 1024; e += 256) { d0[e] = src[e]; d1[e] = src[e + 1024]; }
}

// ---------- prep w (trees): bf16 hi, B-frag n-paired ----------
__global__ __launch_bounds__(256) void k_prep_w(const float* __restrict__ tw) {
    __shared__ __align__(16) unsigned char stage[8192];
    const int tree = blockIdx.x >> 3, kc = blockIdx.x & 7, tid = threadIdx.x;
    for (int e = tid; e < 4096; e += 256) {
        int n = e >> 6, j = e & 63;
        float v = (n < NNODES) ? tw[((size_t)(tree * NNODES + n)) * 512 + kc * 64 + j] : 0.f;
        __nv_bfloat16 h = __float2bfloat16(v);
        int ntile = n >> 3, g = n & 7;
        int kstep = j >> 4, kk = j & 15, tg = (kk >> 1) & 3, regidx = kk >> 3, klo = kk & 1;
        int t = g * 4 + tg;
        uint32_t off = (uint32_t)(((kstep * 4 + (ntile >> 1)) * 32 + t) * 16 +
                                  (ntile & 1) * 8 + regidx * 4 + klo * 2);
        *(__nv_bfloat16*)(stage + off) = h;
    }
    __syncthreads();
    uint4* dst = (uint4*)(g_wf + (size_t)blockIdx.x * 8192);
    const uint4* src = (const uint4*)stage;
    for (int e = tid; e < 512; e += 256) dst[e] = src[e];
}

// ---------- prep w1: bf16 hi/lo, B-frag n-paired (n=128 cols, k=64 per kc) ----------
__global__ __launch_bounds__(256) void k_prep_w1(const float* __restrict__ w1) {
    __shared__ __align__(16) unsigned char stage[32768];
    const int kc = blockIdx.x, tid = threadIdx.x;
    for (int e = tid; e < 8192; e += 256) {
        int n = e >> 6, j = e & 63;
        float v = w1[(size_t)(kc * 64 + j) * 128 + n];
        __nv_bfloat16 h = __float2bfloat16(v);
        __nv_bfloat16 l = __float2bfloat16(v - __bfloat162float(h));
        int ntile = n >> 3, g = n & 7;
        int kstep = j >> 4, kk = j & 15, tg = (kk >> 1) & 3, regidx = kk >> 3, klo = kk & 1;
        int t = g * 4 + tg;
        uint32_t off = (uint32_t)(((kstep * 8 + (ntile >> 1)) * 32 + t) * 16 +
                                  (ntile & 1) * 8 + regidx * 4 + klo * 2);
        *(__nv_bfloat16*)(stage + off) = h;
        *(__nv_bfloat16*)(stage + 16384 + off) = l;
    }
    __syncthreads();
    uint4* dst = (uint4*)(g_w1f + (size_t)kc * 32768);
    const uint4* src = (const uint4*)stage;
    for (int e = tid; e < 2048; e += 256) dst[e] = src[e];
}

// ---------- attention: tensorized phase1 (3-pass hi/lo), SIMT phase2 ----------
__global__ __launch_bounds__(256, 1) void k_attn_mma(
    const float* __restrict__ b1,
    const float* __restrict__ gamma_, const float* __restrict__ beta_,
    const float* __restrict__ mean_, const float* __restrict__ var_,
    const float* __restrict__ w2, const float* __restrict__ b2,
    const float* __restrict__ resw)
{
    extern __shared__ __align__(16) char smp[];
    const uint32_t sm = smem_u32(smp);
    const int tid = threadIdx.x, lane = tid & 31, wid = tid >> 5;
    const int wm = wid & 3, wn = wid >> 2;   // 4 M-tiles(32r) x 2 N-halves(64 cols)
    float* hs = (float*)(smp + AOFF_H);      // [128][132]

    auto issue = [&](int kc) {
        const uint32_t buf = (uint32_t)(kc & 1);
        const unsigned char* xh = g_xf + (size_t)(blockIdx.x * 8 + kc) * 16384;
        const unsigned char* xl = g_xl + (size_t)(blockIdx.x * 8 + kc) * 16384;
        const uint32_t xdst = sm + AOFF_X + buf * 32768;
#pragma unroll
        for (int j = 0; j < 4; ++j) {
            int ch = tid + 256 * j;
            CP16(xdst + ch * 16, xh + ch * 16);
            CP16(xdst + 16384 + ch * 16, xl + ch * 16);
        }
        const unsigned char* ws = g_w1f + (size_t)kc * 32768;
        const uint32_t wdst = sm + AOFF_W + buf * 32768;
#pragma unroll
        for (int j = 0; j < 8; ++j) {
            int ch = tid + 256 * j;
            CP16(wdst + ch * 16, ws + ch * 16);
        }
    };

    float acc[2][8][4];
#pragma unroll
    for (int mi = 0; mi < 2; ++mi)
#pragma unroll
        for (int ni = 0; ni < 8; ++ni)
#pragma unroll
            for (int q = 0; q < 4; ++q) acc[mi][ni][q] = 0.f;

    issue(0);
    CPCOMMIT();
    for (int s = 0; s < 8; ++s) {
        if (s + 1 < 8) { issue(s + 1); CPCOMMIT(); CPWAIT1(); }
        else CPWAIT0();
        __syncthreads();
        const char* bx = smp + AOFF_X + (s & 1) * 32768;
        const char* bw = smp + AOFF_W + (s & 1) * 32768;
#pragma unroll
        for (int ks = 0; ks < 4; ++ks) {
            uint4 ah[2], al[2];
#pragma unroll
            for (int mi = 0; mi < 2; ++mi) {
                uint32_t o = (uint32_t)(((ks * 8 + wm * 2 + mi) * 32 + lane) * 16);
                ah[mi] = *(const uint4*)(bx + o);
                al[mi] = *(const uint4*)(bx + 16384 + o);
            }
#pragma unroll
            for (int p = 0; p < 4; ++p) {
                uint32_t o = (uint32_t)(((ks * 8 + wn * 4 + p) * 32 + lane) * 16);
                uint4 bh = *(const uint4*)(bw + o);
                uint4 bl = *(const uint4*)(bw + 16384 + o);
#pragma unroll
                for (int mi = 0; mi < 2; ++mi) {
                    MMA2(acc[mi][2 * p], ah[mi], bh.x, bh.y);
                    MMA2(acc[mi][2 * p], al[mi], bh.x, bh.y);
                    MMA2(acc[mi][2 * p], ah[mi], bl.x, bl.y);
                    MMA2(acc[mi][2 * p + 1], ah[mi], bh.z, bh.w);
                    MMA2(acc[mi][2 * p + 1], al[mi], bh.z, bh.w);
                    MMA2(acc[mi][2 * p + 1], ah[mi], bl.z, bl.w);
                }
            }
        }
        __syncthreads();
    }
    // fragments -> h smem with bias/relu/BN
#pragma unroll
    for (int ni = 0; ni < 8; ++ni) {
        int c0 = wn * 64 + ni * 8 + (lane & 3) * 2;
        float s0 = gamma_[c0] * rsqrtf(var_[c0] + 1e-5f);
        float s1 = gamma_[c0 + 1] * rsqrtf(var_[c0 + 1] + 1e-5f);
        float o0 = beta_[c0] - mean_[c0] * s0, o1 = beta_[c0 + 1] - mean_[c0 + 1] * s1;
        float bb0 = b1[c0], bb1 = b1[c0 + 1];
#pragma unroll
        for (int mi = 0; mi < 2; ++mi) {
            int r0 = wm * 32 + mi * 16 + (lane >> 2);
            float h0 = fmaxf(acc[mi][ni][0] + bb0, 0.f) * s0 + o0;
            float h1 = fmaxf(acc[mi][ni][1] + bb1, 0.f) * s1 + o1;
            float h2 = fmaxf(acc[mi][ni][2] + bb0, 0.f) * s0 + o0;
            float h3 = fmaxf(acc[mi][ni][3] + bb1, 0.f) * s1 + o1;
            *(float2*)&hs[r0 * 132 + c0] = make_float2(h0, h1);
            *(float2*)&hs[(r0 + 8) * 132 + c0] = make_float2(h2, h3);
        }
    }
    __syncthreads();
    // phase2: logits[128][64] = h @ W2 + b2
    const int tt = tid & 15, rt2 = tid >> 4, t0 = tt * 4, r0b = rt2 * 8;
    float a2[8][4];
#pragma unroll
    for (int i = 0; i < 8; ++i)
#pragma unroll
        for (int j = 0; j < 4; ++j) a2[i][j] = b2[t0 + j];
    const float4* w24 = (const float4*)w2;
#pragma unroll 4
    for (int c = 0; c < 128; ++c) {
        float4 wv = __ldg(&w24[c * 16 + tt]);
#pragma unroll
        for (int i = 0; i < 8; ++i) {
            float h = hs[(r0b + i) * 132 + c];
            a2[i][0] += h * wv.x; a2[i][1] += h * wv.y; a2[i][2] += h * wv.z; a2[i][3] += h * wv.w;
        }
    }
    __syncthreads();
    float* ls = hs;  // reuse
#pragma unroll
    for (int i = 0; i < 8; ++i)
        *(float4*)&ls[(r0b + i) * 68 + t0] = make_float4(a2[i][0], a2[i][1], a2[i][2], a2[i][3]);
    __syncthreads();
    if (tid < 128) {
        int rowg = blockIdx.x * 128 + tid;
        const float* lr = ls + tid * 68;
        float m = -1e30f, s = 0.f;
#pragma unroll 4
        for (int t = 0; t < 64; ++t) m = fmaxf(m, lr[t]);
#pragma unroll 4
        for (int t = 0; t < 64; ++t) s += expf(lr[t] - m);
        float inv = 1.f / s;
#pragma unroll 4
        for (int t = 0; t < 64; ++t) g_attn[t * B_TOTAL + rowg] = expf(lr[t] - m) * inv * (0.3f * resw[t]);
    }
}

// ---------- k_trees: 256 thr / 64 rows / 2 CTAs per SM ----------
__global__ __launch_bounds__(256, 2) void k_trees(
    const float* __restrict__ tree_b, const float* __restrict__ tree_temp,
    const float* __restrict__ leaf_values, float* __restrict__ out)
{
    extern __shared__ __align__(16) char smp[];
    const uint32_t sm = smem_u32(smp);
    const int tid = threadIdx.x, lane = tid & 31, wid = tid >> 5;
    const int wt = wid & 1, wm = (wid >> 1) & 1, wn = (wid >> 2) & 1;
    const int row = tid & 63, part = tid >> 6;
    const int rowg = blockIdx.x * 64 + row;
    const int chalf = blockIdx.x & 1;
    float* lg = (float*)(smp + OFF_LG);
    const int miss = g_missing[rowg];

    float pred[NCLS];
#pragma unroll
    for (int c = 0; c < NCLS; ++c) pred[c] = 0.f;

    const unsigned char* xbase = g_xf + (size_t)(blockIdx.x >> 1) * 8 * 16384;

    auto issue = [&](int s) {
        const int grp = s >> 3, kc = s & 7;
        const uint32_t buf = (uint32_t)(s & 1);
        const unsigned char* xsrc = xbase + (size_t)kc * 16384;
        const uint32_t xdst = sm + OFF_X + buf * 8192;
#pragma unroll
        for (int j = 0; j < 2; ++j) {
            int ch = tid + 256 * j;
            int kstep = ch >> 7, rem = ch & 127;
            CP16(xdst + ch * 16, xsrc + (uint32_t)((kstep * 8 + 4 * chalf) * 512 + rem * 16));
        }
        const unsigned char* wsrc0 = g_wf + ((size_t)(grp * 2) * 8 + kc) * 8192;
        const uint32_t wdst = sm + OFF_W + buf * 16384;
#pragma unroll
        for (int j = 0; j < 2; ++j) {
            int ch = tid + 256 * j;
            CP16(wdst + ch * 16, wsrc0 + ch * 16);
            CP16(wdst + 8192 + ch * 16, wsrc0 + 8 * 8192 + ch * 16);
        }
        if (kc == 0) {
            const unsigned char* lsrc = (const unsigned char*)leaf_values + (size_t)grp * 5120;
            uint32_t ldst = sm + OFF_LEAF + (uint32_t)(grp & 1) * 5120;
            CP16(ldst + tid * 16, lsrc + tid * 16);
            if (tid < 64) CP16(ldst + (tid + 256) * 16, lsrc + (tid + 256) * 16);
        }
    };

    float acc[2][4][4];
#pragma unroll
    for (int mi = 0; mi < 2; ++mi)
#pragma unroll
        for (int ni = 0; ni < 4; ++ni)
#pragma unroll
            for (int q = 0; q < 4; ++q) acc[mi][ni][q] = 0.f;

    issue(0);
    CPCOMMIT();

    for (int s = 0; s < 256; ++s) {
        if (s + 1 < 256) { issue(s + 1); CPCOMMIT(); CPWAIT1(); }
        else CPWAIT0();
        __syncthreads();
        const char* bx = smp + OFF_X + (s & 1) * 8192;
        const char* bw = smp + OFF_W + (s & 1) * 16384 + wt * 8192;
#pragma unroll
        for (int ks = 0; ks < 4; ++ks) {
            uint4 ah[2];
#pragma unroll
            for (int mi = 0; mi < 2; ++mi)
                ah[mi] = *(const uint4*)(bx + (uint32_t)(((ks * 4 + wm * 2 + mi) * 32 + lane) * 16));
#pragma unroll
            for (int ni2 = 0; ni2 < 2; ++ni2) {
                uint4 b = *(const uint4*)(bw + (uint32_t)(((ks * 4 + wn * 2 + ni2) * 32 + lane) * 16));
#pragma unroll
                for (int mi = 0; mi < 2; ++mi) {
                    MMA2(acc[mi][ni2 * 2 + 0], ah[mi], b.x, b.y);
                    MMA2(acc[mi][ni2 * 2 + 1], ah[mi], b.z, b.w);
                }
            }
        }
        __syncthreads();

        if ((s & 7) == 7) {
            const int grp = s >> 3;
#pragma unroll
            for (int mi = 0; mi < 2; ++mi)
#pragma unroll
                for (int ni = 0; ni < 4; ++ni) {
                    int r0 = wm * 32 + mi * 16 + (lane >> 2);
                    int c0 = wt * TOFF + wn * 32 + ni * 8 + (lane & 3) * 2;
                    *(float2*)&lg[r0 * LGP + c0] = make_float2(acc[mi][ni][0], acc[mi][ni][1]);
                    *(float2*)&lg[(r0 + 8) * LGP + c0] = make_float2(acc[mi][ni][2], acc[mi][ni][3]);
                }
            __syncthreads();
            // sigmoid: float2, clamped bias index (col 63 is write-only padding)
#pragma unroll
            for (int tt2 = 0; tt2 < 2; ++tt2) {
                const int t = grp * 2 + tt2;
                float invt = 1.f / tree_temp[t];
                const float* tbp = tree_b + t * NNODES;
#pragma unroll
                for (int j = 0; j < 16; j += 2) {
                    int n = part * 16 + j;
                    float2 v = *(float2*)&lg[row * LGP + tt2 * TOFF + n];
                    float z0 = (v.x + tbp[n]) * invt;
                    float z1 = (v.y + tbp[n + 1 < NNODES ? n + 1 : NNODES - 1]) * invt;
                    z0 = fminf(fmaxf(z0, -30.f), 30.f);
                    z1 = fminf(fmaxf(z1, -30.f), 30.f);
                    float d0 = __fdividef(1.f, 1.f + __expf(-z0));
                    float d1 = __fdividef(1.f, 1.f + __expf(-z1));
                    if (miss) { d0 = 0.5f; d1 = 0.5f; }
                    *(float2*)&lg[row * LGP + tt2 * TOFF + n] = make_float2(d0, d1);
                }
            }
            __syncthreads();
#pragma unroll
            for (int tt2 = 0; tt2 < 2; ++tt2) {
                const int t = grp * 2 + tt2;
                const float* dp = lg + row * LGP + tt2 * TOFF;
                const float* lf = (const float*)(smp + OFF_LEAF + (grp & 1) * 5120) + tt2 * 640;
                float d0 = dp[0], d1 = dp[1], d2 = dp[2];
                float r2[2], r4[4], r8[8];
                r2[0] = d0; r2[1] = 1.f - d0;
                r4[0] = r2[0] * d1; r4[2] = r2[0] - r4[0];
                r4[1] = r2[1] * d2; r4[3] = r2[1] - r4[1];
#pragma unroll
                for (int j = 0; j < 4; ++j) {
                    float d = dp[3 + j];
                    r8[j] = r4[j] * d; r8[j + 4] = r4[j] - r8[j];
                }
                float o[NCLS];
#pragma unroll
                for (int c = 0; c < NCLS; ++c) o[c] = 0.f;
#pragma unroll
                for (int j = 0; j < 8; ++j) {
                    int i = part * 8 + j;
                    float f3 = dp[7 + (i & 7)];   if ((i >> 3) & 1) f3 = 1.f - f3;
                    float f4 = dp[15 + (i & 15)]; if ((i >> 4) & 1) f4 = 1.f - f4;
                    float rr = r8[i & 7] * f3 * f4;
                    float d5 = dp[31 + i];
                    float pL = rr * d5, pR = rr - pL;
                    const float2* lL = (const float2*)(lf + i * 10);
                    const float2* lR = (const float2*)(lf + (i + 32) * 10);
#pragma unroll
                    for (int k = 0; k < 5; ++k) {
                        float2 a = lL[k], b = lR[k];
                        o[2 * k] += pL * a.x + pR * b.x;
                        o[2 * k + 1] += pL * a.y + pR * b.y;
                    }
                }
                float at = g_attn[t * B_TOTAL + rowg];
#pragma unroll
                for (int c = 0; c < NCLS; ++c) pred[c] += at * o[c];
            }
#pragma unroll
            for (int mi = 0; mi < 2; ++mi)
#pragma unroll
                for (int ni = 0; ni < 4; ++ni)
#pragma unroll
                    for (int q = 0; q < 4; ++q) acc[mi][ni][q] = 0.f;
        }
    }

    __syncthreads();
    float* pred_s = lg;
#pragma unroll
    for (int c = 0; c < NCLS; ++c) pred_s[part * 640 + row * 10 + c] = pred[c];
    __syncthreads();
    if (tid < 64) {
#pragma unroll
        for (int c = 0; c < NCLS; ++c)
            pred[c] = pred_s[row * 10 + c] + pred_s[640 + row * 10 + c]
                    + pred_s[1280 + row * 10 + c] + pred_s[1920 + row * 10 + c];
        float m = pred[0];
#pragma unroll
        for (int c = 1; c < NCLS; ++c) m = fmaxf(m, pred[c]);
        float e[NCLS], s = 0.f;
#pragma unroll
        for (int c = 0; c < NCLS; ++c) { e[c] = expf(pred[c] - m); s += e[c]; }
        float inv = 1.f / s;
#pragma unroll
        for (int c = 0; c < NCLS; ++c) out[rowg * 10 + c] = e[c] * inv;
    }
}

// ---------- launcher ----------
extern "C" void kernel_launch(void* const* d_in, const int* in_sizes, int n_in,
                              void* d_out, int out_size) {
    const float* x = (const float*)d_in[0];
    const float* w1 = (const float*)d_in[1];
    const float* b1 = (const float*)d_in[2];
    const float* gm = (const float*)d_in[3];
    const float* bt = (const float*)d_in[4];
    const float* mn = (const float*)d_in[5];
    const float* vr = (const float*)d_in[6];
    const float* w2 = (const float*)d_in[7];
    const float* b2 = (const float*)d_in[8];
    const float* tw = (const float*)d_in[9];
    const float* tb = (const float*)d_in[10];
    const float* tt = (const float*)d_in[11];
    const float* lv = (const float*)d_in[12];
    const float* rw = (const float*)d_in[13];
    cudaFuncSetAttribute(k_trees, cudaFuncAttributeMaxDynamicSharedMemorySize, SMEM_SZ);
    cudaFuncSetAttribute(k_attn_mma, cudaFuncAttributeMaxDynamicSharedMemorySize, ATTN_SMEM);
    k_prep_x<<<1024, 256>>>(x);
    k_prep_w<<<512, 256>>>(tw);
    k_prep_w1<<<8, 256>>>(w1);
    k_attn_mma<<<128, 256, ATTN_SMEM>>>(b1, gm, bt, mn, vr, w2, b2, rw);
    k_trees<<<256, 256, SMEM_SZ>>>(tb, tt, lv, (float*)d_out);
}